// round 1
// baseline (speedup 1.0000x reference)
#include <cuda_runtime.h>

// Problem constants (fixed by the dataset)
static constexpr int N = 50000;
static constexpr int E = 1600000;

// ---------------- scratch (static device allocations are allowed) -----------
__device__ __align__(16) float g_h0[N * 128];
__device__ __align__(16) float g_h1[N * 128];
__device__ int   g_deg[N];
__device__ int   g_row[N + 1];
__device__ int   g_fill[N];
__device__ int   g_csr[E];
__device__ float g_inv[N];

// ---------------- CSR build -------------------------------------------------
__global__ void zero_deg_k() {
    int i = blockIdx.x * blockDim.x + threadIdx.x;
    if (i < N) g_deg[i] = 0;
}

__global__ void count_k(const int* __restrict__ dst) {
    int i = blockIdx.x * blockDim.x + threadIdx.x;
    if (i < E) atomicAdd(&g_deg[dst[i]], 1);
}

// single-block exclusive scan over 50000 ints; also writes fill[] and inv_deg[]
__global__ void scan_k() {
    __shared__ int wsum[32];
    __shared__ int carry;
    int tid = threadIdx.x, lane = tid & 31, wid = tid >> 5;
    if (tid == 0) carry = 0;
    __syncthreads();
    for (int base = 0; base < N; base += 1024) {
        int i = base + tid;
        int v = (i < N) ? g_deg[i] : 0;
        int x = v;
        #pragma unroll
        for (int o = 1; o < 32; o <<= 1) {
            int t = __shfl_up_sync(0xffffffffu, x, o);
            if (lane >= o) x += t;
        }
        if (lane == 31) wsum[wid] = x;
        __syncthreads();
        if (wid == 0) {
            int s = wsum[lane];
            #pragma unroll
            for (int o = 1; o < 32; o <<= 1) {
                int t = __shfl_up_sync(0xffffffffu, s, o);
                if (lane >= o) s += t;
            }
            wsum[lane] = s;
        }
        __syncthreads();
        int excl = x - v + (wid ? wsum[wid - 1] : 0) + carry;
        if (i < N) {
            g_row[i]  = excl;
            g_fill[i] = excl;
            g_inv[i]  = 1.0f / (float)(v > 0 ? v : 1);
        }
        __syncthreads();
        if (tid == 0) carry += wsum[31];
        __syncthreads();
    }
    if (tid == 0) g_row[N] = carry;
}

__global__ void scatter_k(const int* __restrict__ src, const int* __restrict__ dst) {
    int i = blockIdx.x * blockDim.x + threadIdx.x;
    if (i < E) {
        int pos = atomicAdd(&g_fill[dst[i]], 1);
        g_csr[pos] = src[i];
    }
}

// ---------------- fused SAGE layer ------------------------------------------
// Block = 256 threads = 8 warps. Each warp owns 4 nodes:
//   phase 1: mean-aggregate h[src] over the node's CSR range (reg accumulation,
//            float4 per lane covering k = lane*4..lane*4+3), store
//            [self | mean] (256 floats) into smem.
//   phase 2: GEMM: lane owns FOUT/32 contiguous outputs; one W-row vector load
//            feeds FMAs for all 4 nodes (4x W-reuse).
template <int FOUT, bool RELU>
__global__ void __launch_bounds__(256)
sage_k(const float* __restrict__ feat,
       float* __restrict__ dout,
       const float* __restrict__ W,   // [256, FOUT] row-major
       const float* __restrict__ b,   // [FOUT]
       int in_sel, int out_sel) {
    constexpr int JP = FOUT / 32;
    const float* h_in  = (in_sel == 0) ? feat : (in_sel == 1 ? g_h0 : g_h1);
    float*       h_out = (out_sel == 1) ? g_h0 : (out_sel == 2 ? g_h1 : dout);

    __shared__ float sm[32][256];
    int tid = threadIdx.x, lane = tid & 31, w = tid >> 5;
    int node0 = blockIdx.x * 32 + w * 4;

    // ---- phase 1: aggregation ----
    #pragma unroll
    for (int j = 0; j < 4; j++) {
        int node = node0 + j;
        float4 acc  = make_float4(0.f, 0.f, 0.f, 0.f);
        float4 self = make_float4(0.f, 0.f, 0.f, 0.f);
        if (node < N) {
            int beg = g_row[node], end = g_row[node + 1];
            int e = beg;
            for (; e + 4 <= end; e += 4) {
                int s0 = g_csr[e + 0], s1 = g_csr[e + 1];
                int s2 = g_csr[e + 2], s3 = g_csr[e + 3];
                float4 v0 = *(const float4*)(h_in + s0 * 128 + (lane << 2));
                float4 v1 = *(const float4*)(h_in + s1 * 128 + (lane << 2));
                float4 v2 = *(const float4*)(h_in + s2 * 128 + (lane << 2));
                float4 v3 = *(const float4*)(h_in + s3 * 128 + (lane << 2));
                acc.x += (v0.x + v1.x) + (v2.x + v3.x);
                acc.y += (v0.y + v1.y) + (v2.y + v3.y);
                acc.z += (v0.z + v1.z) + (v2.z + v3.z);
                acc.w += (v0.w + v1.w) + (v2.w + v3.w);
            }
            for (; e < end; ++e) {
                int s = g_csr[e];
                float4 v = *(const float4*)(h_in + s * 128 + (lane << 2));
                acc.x += v.x; acc.y += v.y; acc.z += v.z; acc.w += v.w;
            }
            float idg = g_inv[node];
            acc.x *= idg; acc.y *= idg; acc.z *= idg; acc.w *= idg;
            self = *(const float4*)(h_in + node * 128 + (lane << 2));
        }
        int nl = (w << 2) + j;
        *(float4*)&sm[nl][lane << 2]          = self;
        *(float4*)&sm[nl][128 + (lane << 2)]  = acc;
    }
    __syncwarp();   // each warp only touches its own 4 smem rows

    // ---- phase 2: GEMM ----
    float a[4][JP];
    #pragma unroll
    for (int j = 0; j < 4; j++)
        #pragma unroll
        for (int i = 0; i < JP; i++) a[j][i] = 0.f;

    if constexpr (JP == 4) {
        const float4* W4 = (const float4*)W;
        #pragma unroll 4
        for (int k = 0; k < 256; k++) {
            float4 wv = __ldg(&W4[k * (FOUT / 4) + lane]);
            #pragma unroll
            for (int j = 0; j < 4; j++) {
                float hk = sm[(w << 2) + j][k];
                a[j][0] += hk * wv.x;
                a[j][1] += hk * wv.y;
                a[j][2] += hk * wv.z;
                a[j][3] += hk * wv.w;
            }
        }
        float4 bb = __ldg((const float4*)b + lane);
        #pragma unroll
        for (int j = 0; j < 4; j++) {
            int node = node0 + j;
            if (node >= N) continue;
            float4 o = make_float4(a[j][0] + bb.x, a[j][1] + bb.y,
                                   a[j][2] + bb.z, a[j][3] + bb.w);
            if (RELU) {
                o.x = fmaxf(o.x, 0.f); o.y = fmaxf(o.y, 0.f);
                o.z = fmaxf(o.z, 0.f); o.w = fmaxf(o.w, 0.f);
            }
            *(float4*)(h_out + node * FOUT + (lane << 2)) = o;
        }
    } else {
        const float2* W2 = (const float2*)W;
        #pragma unroll 4
        for (int k = 0; k < 256; k++) {
            float2 wv = __ldg(&W2[k * (FOUT / 2) + lane]);
            #pragma unroll
            for (int j = 0; j < 4; j++) {
                float hk = sm[(w << 2) + j][k];
                a[j][0] += hk * wv.x;
                a[j][1] += hk * wv.y;
            }
        }
        float2 bb = __ldg((const float2*)b + lane);
        #pragma unroll
        for (int j = 0; j < 4; j++) {
            int node = node0 + j;
            if (node >= N) continue;
            float2 o = make_float2(a[j][0] + bb.x, a[j][1] + bb.y);
            if (RELU) { o.x = fmaxf(o.x, 0.f); o.y = fmaxf(o.y, 0.f); }
            *(float2*)(h_out + node * FOUT + (lane << 1)) = o;
        }
    }
}

// ---------------- launcher ---------------------------------------------------
extern "C" void kernel_launch(void* const* d_in, const int* in_sizes, int n_in,
                              void* d_out, int out_size) {
    const float* feat = (const float*)d_in[0];
    const int*   src  = (const int*)d_in[1];
    const int*   dst  = (const int*)d_in[2];
    const float* W0   = (const float*)d_in[3];
    const float* b0   = (const float*)d_in[4];
    const float* W1   = (const float*)d_in[5];
    const float* b1   = (const float*)d_in[6];
    const float* W2   = (const float*)d_in[7];
    const float* b2   = (const float*)d_in[8];
    float* out = (float*)d_out;

    const int TB = 256;
    zero_deg_k<<<(N + TB - 1) / TB, TB>>>();
    count_k<<<(E + TB - 1) / TB, TB>>>(dst);
    scan_k<<<1, 1024>>>();
    scatter_k<<<(E + TB - 1) / TB, TB>>>(src, dst);

    int lblocks = (N + 31) / 32;
    sage_k<128, true ><<<lblocks, TB>>>(feat, out, W0, b0, 0, 1);
    sage_k<128, true ><<<lblocks, TB>>>(feat, out, W1, b1, 1, 2);
    sage_k< 64, false><<<lblocks, TB>>>(feat, out, W2, b2, 2, 0);
}